// round 6
// baseline (speedup 1.0000x reference)
#include <cuda_runtime.h>
#include <math.h>

// Shapes
#define B_   32
#define N_   4096
#define C_   128
#define D_   64
#define K_   8
#define H_   128
#define BN_  (B_*N_)          // 131072
#define SLOTS_ (B_*K_)        // 256

// Scratch (device globals; no allocation allowed)
__device__ float g_k[BN_*D_];
__device__ float g_v[BN_*D_];
__device__ float g_q[SLOTS_*D_];
__device__ float g_upd[SLOTS_*D_];
__device__ float g_sums[SLOTS_];
__device__ float g_slot[SLOTS_*D_];
// Transposed GRU weights: [0]=fg_wih^T [1]=fg_whh^T [2]=bg_wih^T [3]=bg_whh^T
// Layout: wT[m][(p*64 + c)*64 + u] = w[m][(p*64 + u)*64 + c]
__device__ float g_wT[4][192*64];

// ---- packed f32x2 helpers (Blackwell FFMA2) --------------------------------
__device__ __forceinline__ unsigned long long pack2(float x) {
    unsigned long long r;
    unsigned xi = __float_as_uint(x);
    asm("mov.b64 %0, {%1, %1};" : "=l"(r) : "r"(xi));
    return r;
}
__device__ __forceinline__ unsigned long long fma2(unsigned long long a,
                                                   unsigned long long b,
                                                   unsigned long long c) {
    unsigned long long d;
    asm("fma.rn.f32x2 %0, %1, %2, %3;" : "=l"(d) : "l"(a), "l"(b), "l"(c));
    return d;
}
__device__ __forceinline__ float2 unpack2(unsigned long long v) {
    unsigned lo, hi;
    asm("mov.b64 {%0, %1}, %2;" : "=r"(lo), "=r"(hi) : "l"(v));
    float2 f;
    f.x = __uint_as_float(lo);
    f.y = __uint_as_float(hi);
    return f;
}

// ---------------------------------------------------------------------------
// Kernel PREP: transpose the 4 GRU weight matrices (per-gate 64x64 transpose).
// ---------------------------------------------------------------------------
__global__ void prep_wT_kernel(const float* __restrict__ fg_wih,
                               const float* __restrict__ fg_whh,
                               const float* __restrict__ bg_wih,
                               const float* __restrict__ bg_whh) {
    const int m = blockIdx.x / 3;
    const int p = blockIdx.x % 3;
    const float* src = (m == 0) ? fg_wih : (m == 1) ? fg_whh
                     : (m == 2) ? bg_wih : bg_whh;
    __shared__ float tile[64][65];
    const int t = threadIdx.x;
    for (int i = t; i < 4096; i += 256) {
        int r = i >> 6, c = i & 63;
        tile[r][c] = src[(p*64 + r)*64 + c];
    }
    __syncthreads();
    for (int i = t; i < 4096; i += 256) {
        int r = i >> 6, c = i & 63;
        g_wT[m][(p*64 + r)*64 + c] = tile[c][r];
    }
}

// ---------------------------------------------------------------------------
// Kernel A (R2/R5 known-good): x = LN(feat); k = x@Wk; v = x@Wv
// ---------------------------------------------------------------------------
__global__ void ln_kv_kernel(const float* __restrict__ feat,
                             const float* __restrict__ gamma,
                             const float* __restrict__ beta,
                             const float* __restrict__ Wk,
                             const float* __restrict__ Wv) {
    extern __shared__ float sm[];
    float* Wc = sm;                 // 128*128
    float* xs = sm + 128*128;       // 64*128

    const int tid  = threadIdx.x;
    const int lane = tid & 31;
    const int warp = tid >> 5;

    for (int idx = tid; idx < 128*64; idx += 256) {
        int c = idx >> 6, d = idx & 63;
        Wc[c*128 + d]      = Wk[idx];
        Wc[c*128 + 64 + d] = Wv[idx];
    }
    const float4 gg = ((const float4*)gamma)[lane];
    const float4 bb = ((const float4*)beta)[lane];
    __syncthreads();

    for (int chunk = blockIdx.x; chunk < BN_/64; chunk += gridDim.x) {
        const int row0 = chunk * 64;
        #pragma unroll
        for (int rr = 0; rr < 8; rr++) {
            int rl = warp*8 + rr;
            float4 xv = ((const float4*)(feat + (size_t)(row0+rl)*128))[lane];
            float s  = xv.x+xv.y+xv.z+xv.w;
            float s2 = xv.x*xv.x + xv.y*xv.y + xv.z*xv.z + xv.w*xv.w;
            #pragma unroll
            for (int o = 16; o > 0; o >>= 1) {
                s  += __shfl_xor_sync(0xffffffffu, s,  o);
                s2 += __shfl_xor_sync(0xffffffffu, s2, o);
            }
            float mean = s * (1.f/128.f);
            float var  = s2 * (1.f/128.f) - mean*mean;
            float rstd = rsqrtf(var + 1e-5f);
            float4 xn;
            xn.x = (xv.x-mean)*rstd*gg.x + bb.x;
            xn.y = (xv.y-mean)*rstd*gg.y + bb.y;
            xn.z = (xv.z-mean)*rstd*gg.z + bb.z;
            xn.w = (xv.w-mean)*rstd*gg.w + bb.w;
            ((float4*)(xs + rl*128))[lane] = xn;
        }
        __syncthreads();

        unsigned long long acc2[8][2];
        #pragma unroll
        for (int ri = 0; ri < 8; ri++) { acc2[ri][0] = 0ULL; acc2[ri][1] = 0ULL; }

        #pragma unroll 2
        for (int c4 = 0; c4 < 32; c4++) {
            float4 xr[8];
            #pragma unroll
            for (int ri = 0; ri < 8; ri++)
                xr[ri] = ((const float4*)(xs + (warp*8+ri)*128))[c4];
            #pragma unroll
            for (int cc = 0; cc < 4; cc++) {
                int c = c4*4 + cc;
                double2 wd = ((const double2*)(Wc + c*128))[lane];
                unsigned long long w01 = __double_as_longlong(wd.x);
                unsigned long long w23 = __double_as_longlong(wd.y);
                #pragma unroll
                for (int ri = 0; ri < 8; ri++) {
                    float xv = (cc == 0) ? xr[ri].x : (cc == 1) ? xr[ri].y
                             : (cc == 2) ? xr[ri].z : xr[ri].w;
                    unsigned long long xx = pack2(xv);
                    acc2[ri][0] = fma2(xx, w01, acc2[ri][0]);
                    acc2[ri][1] = fma2(xx, w23, acc2[ri][1]);
                }
            }
        }
        #pragma unroll
        for (int ri = 0; ri < 8; ri++) {
            int row = row0 + warp*8 + ri;
            float2 a0 = unpack2(acc2[ri][0]);
            float2 a1 = unpack2(acc2[ri][1]);
            float4 o = make_float4(a0.x, a0.y, a1.x, a1.y);
            if (lane < 16) ((float4*)(g_k + (size_t)row*64))[lane]      = o;
            else           ((float4*)(g_v + (size_t)row*64))[lane - 16] = o;
        }
        __syncthreads();
    }
}

// ---------------------------------------------------------------------------
// Kernel Q (initial iteration only): q = LN(slot)@Wq * SCALE; zero accums.
// ---------------------------------------------------------------------------
__global__ void q_kernel(const float* __restrict__ slot_src,
                         const float* __restrict__ qg, const float* __restrict__ qb,
                         const float* __restrict__ Wq,
                         const float* __restrict__ qbgg, const float* __restrict__ qbgb,
                         const float* __restrict__ Wqbg) {
    const int r = blockIdx.x;
    const int t = threadIdx.x;
    const bool bg = (r & 7) == 0;
    const float* g = bg ? qbgg : qg;
    const float* bt = bg ? qbgb : qb;
    const float* W = bg ? Wqbg : Wq;

    __shared__ float xn[64];
    __shared__ float ps[2], ps2[2];

    float x = slot_src[r*64 + t];
    float s = x, s2 = x*x;
    #pragma unroll
    for (int o = 16; o > 0; o >>= 1) {
        s  += __shfl_xor_sync(0xffffffffu, s,  o);
        s2 += __shfl_xor_sync(0xffffffffu, s2, o);
    }
    if ((t & 31) == 0) { ps[t>>5] = s; ps2[t>>5] = s2; }
    __syncthreads();
    s = ps[0] + ps[1]; s2 = ps2[0] + ps2[1];
    float mean = s * (1.f/64.f);
    float var  = s2 * (1.f/64.f) - mean*mean;
    float rstd = rsqrtf(var + 1e-5f);
    xn[t] = (x - mean)*rstd*g[t] + bt[t];
    __syncthreads();

    float a0 = 0.f, a1 = 0.f;
    #pragma unroll 8
    for (int c = 0; c < 64; c += 2) {
        a0 += xn[c]  *__ldg(W + c*64 + t);
        a1 += xn[c+1]*__ldg(W + (c+1)*64 + t);
    }
    g_q[r*64 + t] = (a0 + a1) * 0.125f;   // SCALE folded in

    g_upd[r*64 + t] = 0.f;
    if (t == 0) g_sums[r] = 0.f;
}

// ---------------------------------------------------------------------------
// Kernel ATTN (R5 known-good): single 256-j tile per block, grid (16, B).
// ---------------------------------------------------------------------------
__global__ void attn_kernel(float* __restrict__ attn_out) {   // may be null
    const int b  = blockIdx.y;
    const int j0 = blockIdx.x * 256;
    const int t  = threadIdx.x;

    __shared__ float qsh[512];
    __shared__ float ash[8][256];

    for (int idx = t; idx < 512; idx += 256) qsh[idx] = g_q[b*512 + idx];
    __syncthreads();

    const float4* kp = (const float4*)(g_k + ((size_t)b*N_ + j0 + t)*64);
    float dots[8];
    #pragma unroll
    for (int i = 0; i < 8; i++) dots[i] = 0.f;
    #pragma unroll
    for (int cc = 0; cc < 16; cc++) {
        float4 kk = __ldg(kp + cc);
        #pragma unroll
        for (int i = 0; i < 8; i++) {
            float4 qv = ((const float4*)(qsh + i*64))[cc];
            dots[i] += kk.x*qv.x + kk.y*qv.y + kk.z*qv.z + kk.w*qv.w;
        }
    }
    float mx = -1e30f;
    #pragma unroll
    for (int i = 0; i < 8; i++) mx = fmaxf(mx, dots[i]);
    float e[8], se = 0.f;
    #pragma unroll
    for (int i = 0; i < 8; i++) { e[i] = __expf(dots[i] - mx); se += e[i]; }
    float inv = 1.f / se;
    #pragma unroll
    for (int i = 0; i < 8; i++) {
        float a = e[i]*inv + 1e-8f;
        ash[i][t] = a;
        if (attn_out)
            attn_out[((size_t)(b*8 + i))*N_ + j0 + t] = a;
    }
    __syncthreads();

    {
        int w = t >> 5, lane = t & 31;
        float s = 0.f;
        #pragma unroll
        for (int q8 = 0; q8 < 8; q8++) s += ash[w][lane + 32*q8];
        #pragma unroll
        for (int o = 16; o > 0; o >>= 1) s += __shfl_xor_sync(0xffffffffu, s, o);
        if (lane == 0) atomicAdd(&g_sums[b*8 + w], s);
    }

    const int d4    = t & 15;
    const int i8    = (t >> 4) & 7;
    const int jhalf = (t >> 7) * 128;
    float4 up = make_float4(0.f, 0.f, 0.f, 0.f);
    const float4* vp = (const float4*)(g_v + ((size_t)b*N_ + j0 + jhalf)*64);
    #pragma unroll 4
    for (int j = 0; j < 128; j++) {
        float4 vv = __ldg(vp + j*16 + d4);
        float a = ash[i8][jhalf + j];
        up.x += a*vv.x; up.y += a*vv.y; up.z += a*vv.z; up.w += a*vv.w;
    }
    float* ub = &g_upd[((size_t)(b*8) + i8)*64 + d4*4];
    atomicAdd(ub+0, up.x); atomicAdd(ub+1, up.y);
    atomicAdd(ub+2, up.z); atomicAdd(ub+3, up.w);
}

// ---------------------------------------------------------------------------
// Kernel UPDATE v5: grid 256 (one block per slot row) x 128 threads.
// Thread halves split the wih/whh chains, MLP w2, and fused-q columns.
// Transposed GRU weights -> coalesced direct LDG (L2-resident), no staging.
// Fuses the NEXT iteration's q projection (q = LN(o)@Wq * SCALE).
// ---------------------------------------------------------------------------
__global__ void __launch_bounds__(128)
update_kernel(const float* __restrict__ slot_src,   // null -> g_slot
    const float* __restrict__ fg_bih, const float* __restrict__ fg_bhh,
    const float* __restrict__ bg_bih, const float* __restrict__ bg_bhh,
    const float* __restrict__ fg_lng, const float* __restrict__ fg_lnb,
    const float* __restrict__ fg_w1,  const float* __restrict__ fg_b1,
    const float* __restrict__ fg_w2,  const float* __restrict__ fg_b2,
    const float* __restrict__ bg_lng, const float* __restrict__ bg_lnb,
    const float* __restrict__ bg_w1,  const float* __restrict__ bg_b1,
    const float* __restrict__ bg_w2,  const float* __restrict__ bg_b2,
    const float* __restrict__ qg, const float* __restrict__ qb,
    const float* __restrict__ Wq,
    const float* __restrict__ qbgg, const float* __restrict__ qbgb,
    const float* __restrict__ Wqbg,
    float* __restrict__ out_slots) {
    const int r    = blockIdx.x;
    const int t    = threadIdx.x;
    const int half = t >> 6;
    const int u    = t & 63;
    const bool bg  = (r & 7) == 0;
    const float* sp = slot_src ? slot_src : g_slot;

    __shared__ float vecs[2][64];    // [0]=su (normalized upd), [1]=sh / later o
    __shared__ float ssh[64];        // GRU output s
    __shared__ float gsh[6][64];     // gi[0..2], gh[0..2]
    __shared__ float sx[64];         // LN output (reused)
    __shared__ float hb[128];        // MLP hidden
    __shared__ float po[2][64];      // partial sums
    __shared__ float ps[4], ps2[4];

    if (half == 0) vecs[0][u] = g_upd[r*64 + u] / g_sums[r];
    else           vecs[1][u] = sp[r*64 + u];
    __syncthreads();

    // ---- GRU gates: half 0 -> su@wih^T, half 1 -> sh@whh^T ----
    const float* wT   = (half == 0) ? (bg ? g_wT[2] : g_wT[0])
                                    : (bg ? g_wT[3] : g_wT[1]);
    const float* bias = (half == 0) ? (bg ? bg_bih : fg_bih)
                                    : (bg ? bg_bhh : fg_bhh);
    const float* vec  = vecs[half];
    #pragma unroll
    for (int p = 0; p < 3; p++) {
        const float* wp = wT + (size_t)(p*64)*64 + u;
        float a0 = 0.f, a1 = 0.f, a2 = 0.f, a3 = 0.f;
        #pragma unroll
        for (int c = 0; c < 64; c += 4) {
            a0 += vec[c]  *__ldg(wp + (size_t)(c  )*64);
            a1 += vec[c+1]*__ldg(wp + (size_t)(c+1)*64);
            a2 += vec[c+2]*__ldg(wp + (size_t)(c+2)*64);
            a3 += vec[c+3]*__ldg(wp + (size_t)(c+3)*64);
        }
        gsh[half*3 + p][u] = (a0 + a1) + (a2 + a3) + bias[p*64 + u];
    }
    __syncthreads();

    // ---- gate combine (half 0 only), then LN(s) ----
    float s = 0.f;
    if (half == 0) {
        float hval = vecs[1][u];
        float rg = 1.f/(1.f + __expf(-(gsh[0][u] + gsh[3][u])));
        float z  = 1.f/(1.f + __expf(-(gsh[1][u] + gsh[4][u])));
        float n  = tanhf(gsh[2][u] + rg*gsh[5][u]);
        s = (1.f - z)*n + z*hval;
        ssh[u] = s;
    }
    float a = s, a2v = s*s;
    #pragma unroll
    for (int o = 16; o > 0; o >>= 1) {
        a   += __shfl_xor_sync(0xffffffffu, a,   o);
        a2v += __shfl_xor_sync(0xffffffffu, a2v, o);
    }
    if ((t & 31) == 0) { ps[t>>5] = a; ps2[t>>5] = a2v; }
    __syncthreads();
    {
        float tot = ps[0] + ps[1], tot2 = ps2[0] + ps2[1];
        float mean = tot * (1.f/64.f);
        float var  = tot2 * (1.f/64.f) - mean*mean;
        float rstd = rsqrtf(var + 1e-5f);
        if (half == 0) {
            const float* lng = bg ? bg_lng : fg_lng;
            const float* lnb = bg ? bg_lnb : fg_lnb;
            sx[u] = (s - mean)*rstd*lng[u] + lnb[u];
        }
    }
    __syncthreads();

    // ---- MLP layer 1: all 128 threads, one hidden unit each ----
    {
        const float* w1 = bg ? bg_w1 : fg_w1;
        const float* b1 = bg ? bg_b1 : fg_b1;
        float h0 = b1[t], h1 = 0.f, h2 = 0.f, h3 = 0.f;
        #pragma unroll
        for (int c = 0; c < 64; c += 4) {
            h0 += sx[c]  *__ldg(w1 + (c  )*128 + t);
            h1 += sx[c+1]*__ldg(w1 + (c+1)*128 + t);
            h2 += sx[c+2]*__ldg(w1 + (c+2)*128 + t);
            h3 += sx[c+3]*__ldg(w1 + (c+3)*128 + t);
        }
        hb[t] = fmaxf((h0 + h1) + (h2 + h3), 0.f);
    }
    __syncthreads();

    // ---- MLP layer 2: column-split across halves ----
    {
        const float* w2 = bg ? bg_w2 : fg_w2;
        float o0 = 0.f, o1 = 0.f, o2 = 0.f, o3 = 0.f;
        const int hh0 = half * 64;
        #pragma unroll
        for (int hh = 0; hh < 64; hh += 4) {
            o0 += hb[hh0+hh]  *__ldg(w2 + (hh0+hh  )*64 + u);
            o1 += hb[hh0+hh+1]*__ldg(w2 + (hh0+hh+1)*64 + u);
            o2 += hb[hh0+hh+2]*__ldg(w2 + (hh0+hh+2)*64 + u);
            o3 += hb[hh0+hh+3]*__ldg(w2 + (hh0+hh+3)*64 + u);
        }
        po[half][u] = (o0 + o1) + (o2 + o3);
    }
    __syncthreads();

    float o = 0.f;
    if (half == 0) {
        const float* b2 = bg ? bg_b2 : fg_b2;
        o = ssh[u] + b2[u] + po[0][u] + po[1][u];
        g_slot[r*64 + u] = o;
        if (out_slots) out_slots[r*64 + u] = o;
        vecs[1][u] = o;    // stash for nothing else; keeps o visible if needed
    }

    // ---- fused q for NEXT iteration: LN(o) @ Wq * SCALE ----
    a = o; a2v = o*o;
    #pragma unroll
    for (int off = 16; off > 0; off >>= 1) {
        a   += __shfl_xor_sync(0xffffffffu, a,   off);
        a2v += __shfl_xor_sync(0xffffffffu, a2v, off);
    }
    __syncthreads();   // po reads done before reuse; ps reuse safe
    if ((t & 31) == 0) { ps[t>>5] = a; ps2[t>>5] = a2v; }
    __syncthreads();
    {
        float tot = ps[0] + ps[1], tot2 = ps2[0] + ps2[1];
        float mean = tot * (1.f/64.f);
        float var  = tot2 * (1.f/64.f) - mean*mean;
        float rstd = rsqrtf(var + 1e-5f);
        if (half == 0) {
            const float* qgp = bg ? qbgg : qg;
            const float* qbp = bg ? qbgb : qb;
            sx[u] = (o - mean)*rstd*qgp[u] + qbp[u];
        }
    }
    __syncthreads();

    {
        const float* Wp = bg ? Wqbg : Wq;
        const int c0 = half * 32;
        float q0 = 0.f, q1 = 0.f;
        #pragma unroll
        for (int c = 0; c < 32; c += 2) {
            q0 += sx[c0+c]  *__ldg(Wp + (c0+c  )*64 + u);
            q1 += sx[c0+c+1]*__ldg(Wp + (c0+c+1)*64 + u);
        }
        po[half][u] = q0 + q1;
    }
    __syncthreads();
    if (half == 0) {
        g_q[r*64 + u] = (po[0][u] + po[1][u]) * 0.125f;
        g_upd[r*64 + u] = 0.f;           // reset for next attn
    }
    if (t == 0) g_sums[r] = 0.f;
}

// ---------------------------------------------------------------------------
extern "C" void kernel_launch(void* const* d_in, const int* in_sizes, int n_in,
                              void* d_out, int out_size) {
    const float* feat   = (const float*)d_in[0];
    const float* slot   = (const float*)d_in[1];
    const float* nfg    = (const float*)d_in[2];
    const float* nfb    = (const float*)d_in[3];
    const float* Wk     = (const float*)d_in[4];
    const float* Wv     = (const float*)d_in[5];
    const float* qg     = (const float*)d_in[6];
    const float* qb     = (const float*)d_in[7];
    const float* Wq     = (const float*)d_in[8];
    const float* qbgg   = (const float*)d_in[9];
    const float* qbgb   = (const float*)d_in[10];
    const float* Wqbg   = (const float*)d_in[11];
    const float* gwih   = (const float*)d_in[12];
    const float* gwhh   = (const float*)d_in[13];
    const float* gbih   = (const float*)d_in[14];
    const float* gbhh   = (const float*)d_in[15];
    const float* bgwih  = (const float*)d_in[16];
    const float* bgwhh  = (const float*)d_in[17];
    const float* bgbih  = (const float*)d_in[18];
    const float* bgbhh  = (const float*)d_in[19];
    const float* rlng   = (const float*)d_in[20];
    const float* rlnb   = (const float*)d_in[21];
    const float* rw1    = (const float*)d_in[22];
    const float* rb1    = (const float*)d_in[23];
    const float* rw2    = (const float*)d_in[24];
    const float* rb2    = (const float*)d_in[25];
    const float* bglng  = (const float*)d_in[26];
    const float* bglnb  = (const float*)d_in[27];
    const float* bgw1   = (const float*)d_in[28];
    const float* bgb1   = (const float*)d_in[29];
    const float* bgw2   = (const float*)d_in[30];
    const float* bgb2   = (const float*)d_in[31];

    float* out       = (float*)d_out;
    float* out_attn  = out + SLOTS_*D_;   // slots first, then attn

    const int smem_lnkv = (128*128 + 64*128) * (int)sizeof(float);  // 98304 B
    cudaFuncSetAttribute(ln_kv_kernel,
                         cudaFuncAttributeMaxDynamicSharedMemorySize, smem_lnkv);

    prep_wT_kernel<<<12, 256>>>(gwih, gwhh, bgwih, bgwhh);
    ln_kv_kernel<<<296, 256, smem_lnkv>>>(feat, nfg, nfb, Wk, Wv);
    q_kernel<<<SLOTS_, 64>>>(slot, qg, qb, Wq, qbgg, qbgb, Wqbg);

    for (int it = 0; it < 3; it++) {
        attn_kernel<<<dim3(16, B_), 256>>>((it == 2) ? out_attn : nullptr);
        update_kernel<<<SLOTS_, 128>>>((it == 0) ? slot : nullptr,
            gbih, gbhh, bgbih, bgbhh,
            rlng, rlnb, rw1, rb1, rw2, rb2,
            bglng, bglnb, bgw1, bgb1, bgw2, bgb2,
            qg, qb, Wq, qbgg, qbgb, Wqbg,
            (it == 2) ? out : nullptr);
    }
}

// round 7
// speedup vs baseline: 1.0594x; 1.0594x over previous
#include <cuda_runtime.h>
#include <math.h>

// Shapes
#define B_   32
#define N_   4096
#define C_   128
#define D_   64
#define K_   8
#define H_   128
#define BN_  (B_*N_)          // 131072
#define SLOTS_ (B_*K_)        // 256

// Scratch (device globals; no allocation allowed)
__device__ float g_kT[B_*D_*N_];   // transposed k: [b][d][j]
__device__ float g_v[BN_*D_];
__device__ float g_q[SLOTS_*D_];
__device__ float g_upd[SLOTS_*D_];
__device__ float g_sums[SLOTS_];
__device__ float g_slot[SLOTS_*D_];

// ---- packed f32x2 helpers (Blackwell FFMA2) --------------------------------
__device__ __forceinline__ unsigned long long pack2(float x) {
    unsigned long long r;
    unsigned xi = __float_as_uint(x);
    asm("mov.b64 %0, {%1, %1};" : "=l"(r) : "r"(xi));
    return r;
}
__device__ __forceinline__ unsigned long long packab(float lo, float hi) {
    unsigned long long r;
    asm("mov.b64 %0, {%1, %2};" : "=l"(r)
        : "r"(__float_as_uint(lo)), "r"(__float_as_uint(hi)));
    return r;
}
__device__ __forceinline__ unsigned long long fma2(unsigned long long a,
                                                   unsigned long long b,
                                                   unsigned long long c) {
    unsigned long long d;
    asm("fma.rn.f32x2 %0, %1, %2, %3;" : "=l"(d) : "l"(a), "l"(b), "l"(c));
    return d;
}
__device__ __forceinline__ float2 unpack2(unsigned long long v) {
    unsigned lo, hi;
    asm("mov.b64 {%0, %1}, %2;" : "=r"(lo), "=r"(hi) : "l"(v));
    float2 f;
    f.x = __uint_as_float(lo);
    f.y = __uint_as_float(hi);
    return f;
}

// ---------------------------------------------------------------------------
// Kernel A: x = LN(feat); kT = (x@Wk)^T (via SMEM transpose); v = x@Wv
// ---------------------------------------------------------------------------
__global__ void ln_kv_kernel(const float* __restrict__ feat,
                             const float* __restrict__ gamma,
                             const float* __restrict__ beta,
                             const float* __restrict__ Wk,
                             const float* __restrict__ Wv) {
    extern __shared__ float sm[];
    float* Wc = sm;                 // 128*128
    float* xs = sm + 128*128;       // 64*128 (x tile; reused as k-transpose stage)

    const int tid  = threadIdx.x;
    const int lane = tid & 31;
    const int warp = tid >> 5;

    for (int idx = tid; idx < 128*64; idx += 256) {
        int c = idx >> 6, d = idx & 63;
        Wc[c*128 + d]      = Wk[idx];
        Wc[c*128 + 64 + d] = Wv[idx];
    }
    const float4 gg = ((const float4*)gamma)[lane];
    const float4 bb = ((const float4*)beta)[lane];
    __syncthreads();

    for (int chunk = blockIdx.x; chunk < BN_/64; chunk += gridDim.x) {
        const int row0 = chunk * 64;
        // ---- LN phase ----
        #pragma unroll
        for (int rr = 0; rr < 8; rr++) {
            int rl = warp*8 + rr;
            float4 xv = ((const float4*)(feat + (size_t)(row0+rl)*128))[lane];
            float s  = xv.x+xv.y+xv.z+xv.w;
            float s2 = xv.x*xv.x + xv.y*xv.y + xv.z*xv.z + xv.w*xv.w;
            #pragma unroll
            for (int o = 16; o > 0; o >>= 1) {
                s  += __shfl_xor_sync(0xffffffffu, s,  o);
                s2 += __shfl_xor_sync(0xffffffffu, s2, o);
            }
            float mean = s * (1.f/128.f);
            float var  = s2 * (1.f/128.f) - mean*mean;
            float rstd = rsqrtf(var + 1e-5f);
            float4 xn;
            xn.x = (xv.x-mean)*rstd*gg.x + bb.x;
            xn.y = (xv.y-mean)*rstd*gg.y + bb.y;
            xn.z = (xv.z-mean)*rstd*gg.z + bb.z;
            xn.w = (xv.w-mean)*rstd*gg.w + bb.w;
            ((float4*)(xs + rl*128))[lane] = xn;
        }
        __syncthreads();

        // ---- GEMM: thread = 8 rows x 4 cols (lane<16: k cols, else v) ----
        unsigned long long acc2[8][2];
        #pragma unroll
        for (int ri = 0; ri < 8; ri++) { acc2[ri][0] = 0ULL; acc2[ri][1] = 0ULL; }

        #pragma unroll 2
        for (int c4 = 0; c4 < 32; c4++) {
            float4 xr[8];
            #pragma unroll
            for (int ri = 0; ri < 8; ri++)
                xr[ri] = ((const float4*)(xs + (warp*8+ri)*128))[c4];
            #pragma unroll
            for (int cc = 0; cc < 4; cc++) {
                int c = c4*4 + cc;
                double2 wd = ((const double2*)(Wc + c*128))[lane];
                unsigned long long w01 = __double_as_longlong(wd.x);
                unsigned long long w23 = __double_as_longlong(wd.y);
                #pragma unroll
                for (int ri = 0; ri < 8; ri++) {
                    float xv = (cc == 0) ? xr[ri].x : (cc == 1) ? xr[ri].y
                             : (cc == 2) ? xr[ri].z : xr[ri].w;
                    unsigned long long xx = pack2(xv);
                    acc2[ri][0] = fma2(xx, w01, acc2[ri][0]);
                    acc2[ri][1] = fma2(xx, w23, acc2[ri][1]);
                }
            }
        }
        __syncthreads();   // xs reads complete -> safe to reuse as stage

        // ---- write-back: k -> SMEM transpose stage, v -> direct global ----
        float* kstage = xs;   // 64 d-rows, stride 68 (2-way max bank conflict)
        if (lane < 16) {
            #pragma unroll
            for (int ri = 0; ri < 8; ri++) {
                int jl = warp*8 + ri;
                float2 a0 = unpack2(acc2[ri][0]);
                float2 a1 = unpack2(acc2[ri][1]);
                kstage[(4*lane+0)*68 + jl] = a0.x;
                kstage[(4*lane+1)*68 + jl] = a0.y;
                kstage[(4*lane+2)*68 + jl] = a1.x;
                kstage[(4*lane+3)*68 + jl] = a1.y;
            }
        } else {
            #pragma unroll
            for (int ri = 0; ri < 8; ri++) {
                size_t row = (size_t)(row0 + warp*8 + ri);
                float2 a0 = unpack2(acc2[ri][0]);
                float2 a1 = unpack2(acc2[ri][1]);
                ((float4*)(g_v + row*64))[lane - 16] =
                    make_float4(a0.x, a0.y, a1.x, a1.y);
            }
        }
        __syncthreads();

        // ---- coalesced transposed k store: g_kT[b][d][j0..j0+63] ----
        {
            const size_t bb = (size_t)(row0 >> 12);
            const int jj0 = row0 & 4095;
            for (int idx = tid; idx < 1024; idx += 256) {
                int d = idx >> 4, q = (idx & 15) * 4;
                float4 val = *(const float4*)(kstage + d*68 + q);
                *(float4*)(g_kT + (bb*64 + d)*4096 + jj0 + q) = val;
            }
        }
        __syncthreads();   // before next chunk overwrites xs
    }
}

// ---------------------------------------------------------------------------
// Kernel Q: q = LN(slot)@Wq * SCALE; zero accumulators.
// ---------------------------------------------------------------------------
__global__ void q_kernel(const float* __restrict__ slot_src,  // null -> g_slot
                         const float* __restrict__ qg, const float* __restrict__ qb,
                         const float* __restrict__ Wq,
                         const float* __restrict__ qbgg, const float* __restrict__ qbgb,
                         const float* __restrict__ Wqbg) {
    const int r = blockIdx.x;
    const int t = threadIdx.x;
    const bool bg = (r & 7) == 0;
    const float* g = bg ? qbgg : qg;
    const float* bt = bg ? qbgb : qb;
    const float* W = bg ? Wqbg : Wq;
    const float* sp = slot_src ? slot_src : g_slot;

    __shared__ float xn[64];
    __shared__ float ps[2], ps2[2];

    float x = sp[r*64 + t];
    float s = x, s2 = x*x;
    #pragma unroll
    for (int o = 16; o > 0; o >>= 1) {
        s  += __shfl_xor_sync(0xffffffffu, s,  o);
        s2 += __shfl_xor_sync(0xffffffffu, s2, o);
    }
    if ((t & 31) == 0) { ps[t>>5] = s; ps2[t>>5] = s2; }
    __syncthreads();
    s = ps[0] + ps[1]; s2 = ps2[0] + ps2[1];
    float mean = s * (1.f/64.f);
    float var  = s2 * (1.f/64.f) - mean*mean;
    float rstd = rsqrtf(var + 1e-5f);
    xn[t] = (x - mean)*rstd*g[t] + bt[t];
    __syncthreads();

    float a0 = 0.f, a1 = 0.f;
    #pragma unroll 8
    for (int c = 0; c < 64; c += 2) {
        a0 += xn[c]  *__ldg(W + c*64 + t);
        a1 += xn[c+1]*__ldg(W + (c+1)*64 + t);
    }
    g_q[r*64 + t] = (a0 + a1) * 0.125f;   // SCALE folded in

    g_upd[r*64 + t] = 0.f;
    if (t == 0) g_sums[r] = 0.f;
}

// ---------------------------------------------------------------------------
// Kernel ATTN v7: coalesced kT reads + slot-pair f32x2 dots.
// grid (16, B), 256 threads, one 256-j tile per block.
// ---------------------------------------------------------------------------
__global__ void attn_kernel(float* __restrict__ attn_out) {   // may be null
    const int b  = blockIdx.y;
    const int j0 = blockIdx.x * 256;
    const int t  = threadIdx.x;

    __shared__ unsigned long long qp[4][64];   // (slot 2p, 2p+1) pairs per dim c
    __shared__ float ash[8][256];

    {   // build pair table (coalesced g_q reads)
        int p = t >> 6, c = t & 63;
        float lo = g_q[b*512 + (2*p)*64 + c];
        float hi = g_q[b*512 + (2*p+1)*64 + c];
        qp[p][c] = packab(lo, hi);
    }
    __syncthreads();

    // ---- phase 1: thread t owns j = j0 + t; coalesced kT loads ----
    const float* kTb = g_kT + (size_t)(b*64)*4096 + j0 + t;
    unsigned long long dp[4] = {0ULL, 0ULL, 0ULL, 0ULL};
    #pragma unroll 8
    for (int c = 0; c < 64; c++) {
        unsigned long long kc = pack2(__ldg(kTb + (size_t)c*4096));
        dp[0] = fma2(kc, qp[0][c], dp[0]);
        dp[1] = fma2(kc, qp[1][c], dp[1]);
        dp[2] = fma2(kc, qp[2][c], dp[2]);
        dp[3] = fma2(kc, qp[3][c], dp[3]);
    }
    float dots[8];
    #pragma unroll
    for (int p = 0; p < 4; p++) {
        float2 d2 = unpack2(dp[p]);
        dots[2*p]   = d2.x;
        dots[2*p+1] = d2.y;
    }
    float mx = -1e30f;
    #pragma unroll
    for (int i = 0; i < 8; i++) mx = fmaxf(mx, dots[i]);
    float e[8], se = 0.f;
    #pragma unroll
    for (int i = 0; i < 8; i++) { e[i] = __expf(dots[i] - mx); se += e[i]; }
    float inv = 1.f / se;
    #pragma unroll
    for (int i = 0; i < 8; i++) {
        float a = e[i]*inv + 1e-8f;
        ash[i][t] = a;
        if (attn_out)
            attn_out[((size_t)(b*8 + i))*N_ + j0 + t] = a;
    }
    __syncthreads();

    // ---- rowsums ----
    {
        int w = t >> 5, lane = t & 31;
        float s = 0.f;
        #pragma unroll
        for (int q8 = 0; q8 < 8; q8++) s += ash[w][lane + 32*q8];
        #pragma unroll
        for (int o = 16; o > 0; o >>= 1) s += __shfl_xor_sync(0xffffffffu, s, o);
        if (lane == 0) atomicAdd(&g_sums[b*8 + w], s);
    }

    // ---- phase 2: un-normalized attn @ v ----
    const int d4    = t & 15;
    const int i8    = (t >> 4) & 7;
    const int jhalf = (t >> 7) * 128;
    float4 up = make_float4(0.f, 0.f, 0.f, 0.f);
    const float4* vp = (const float4*)(g_v + ((size_t)b*N_ + j0 + jhalf)*64);
    #pragma unroll 4
    for (int j = 0; j < 128; j++) {
        float4 vv = __ldg(vp + j*16 + d4);
        float a = ash[i8][jhalf + j];
        up.x += a*vv.x; up.y += a*vv.y; up.z += a*vv.z; up.w += a*vv.w;
    }
    float* ub = &g_upd[((size_t)(b*8) + i8)*64 + d4*4];
    atomicAdd(ub+0, up.x); atomicAdd(ub+1, up.y);
    atomicAdd(ub+2, up.z); atomicAdd(ub+3, up.w);
}

// ---------------------------------------------------------------------------
// Kernel UPDATE (R2/R5 known-good): one block per batch, 512 threads.
// ---------------------------------------------------------------------------
#define TP_ 65   // padded tile row stride
__global__ void update_kernel(const float* __restrict__ slot_src,  // null -> g_slot
    const float* __restrict__ fg_wih, const float* __restrict__ fg_whh,
    const float* __restrict__ fg_bih, const float* __restrict__ fg_bhh,
    const float* __restrict__ bg_wih, const float* __restrict__ bg_whh,
    const float* __restrict__ bg_bih, const float* __restrict__ bg_bhh,
    const float* __restrict__ fg_lng, const float* __restrict__ fg_lnb,
    const float* __restrict__ fg_w1,  const float* __restrict__ fg_b1,
    const float* __restrict__ fg_w2,  const float* __restrict__ fg_b2,
    const float* __restrict__ bg_lng, const float* __restrict__ bg_lnb,
    const float* __restrict__ bg_w1,  const float* __restrict__ bg_b1,
    const float* __restrict__ bg_w2,  const float* __restrict__ bg_b2,
    float* __restrict__ out_slots) {
    extern __shared__ float dsm[];
    float* s_wih_fg = dsm;                 // 64*TP_
    float* s_whh_fg = s_wih_fg + 64*TP_;
    float* s_wih_bg = s_whh_fg + 64*TP_;
    float* s_whh_bg = s_wih_bg + 64*TP_;

    __shared__ float su[8][64], sh[8][64], sx[8][64], hb[8][128];
    __shared__ float ps[16], ps2[16];

    const int b = blockIdx.x;
    const int t = threadIdx.x;
    const int g = t >> 6;
    const int u = t & 63;
    const int r = b*8 + g;
    const bool bg = (g == 0);
    const float* sp = slot_src ? slot_src : g_slot;

    float inv = 1.f / g_sums[r];
    su[g][u] = g_upd[r*64 + u] * inv;
    float h = sp[r*64 + u];
    sh[g][u] = h;

    const float* bih = bg ? bg_bih : fg_bih;
    const float* bhh = bg ? bg_bhh : fg_bhh;

    float gi[3], gh[3];
    #pragma unroll 1
    for (int p = 0; p < 3; p++) {
        __syncthreads();
        for (int idx = t; idx < 4096; idx += 512) {
            int row = idx >> 6, col = idx & 63;
            int gix = (p*64 + row)*64 + col;
            s_wih_fg[row*TP_ + col] = fg_wih[gix];
            s_whh_fg[row*TP_ + col] = fg_whh[gix];
            s_wih_bg[row*TP_ + col] = bg_wih[gix];
            s_whh_bg[row*TP_ + col] = bg_whh[gix];
        }
        __syncthreads();
        const float* wi = (bg ? s_wih_bg : s_wih_fg) + u*TP_;
        const float* wh = (bg ? s_whh_bg : s_whh_fg) + u*TP_;
        float ai = bih[p*64 + u], ah = bhh[p*64 + u];
        #pragma unroll 8
        for (int c = 0; c < 64; c++) {
            ai += su[g][c]*wi[c];
            ah += sh[g][c]*wh[c];
        }
        gi[p] = ai; gh[p] = ah;
    }

    float rg = 1.f/(1.f + __expf(-(gi[0] + gh[0])));
    float z  = 1.f/(1.f + __expf(-(gi[1] + gh[1])));
    float n  = tanhf(gi[2] + rg*gh[2]);
    float s  = (1.f - z)*n + z*h;

    const float* lng = bg ? bg_lng : fg_lng;
    const float* lnb = bg ? bg_lnb : fg_lnb;
    float a = s, a2 = s*s;
    #pragma unroll
    for (int o = 16; o > 0; o >>= 1) {
        a  += __shfl_xor_sync(0xffffffffu, a,  o);
        a2 += __shfl_xor_sync(0xffffffffu, a2, o);
    }
    int w = t >> 5;
    if ((t & 31) == 0) { ps[w] = a; ps2[w] = a2; }
    __syncthreads();
    a  = ps[g*2]  + ps[g*2+1];
    a2 = ps2[g*2] + ps2[g*2+1];
    float mean = a * (1.f/64.f);
    float var  = a2 * (1.f/64.f) - mean*mean;
    float rstd = rsqrtf(var + 1e-5f);
    sx[g][u] = (s - mean)*rstd*lng[u] + lnb[u];
    __syncthreads();

    const float* w1 = bg ? bg_w1 : fg_w1;
    const float* b1 = bg ? bg_b1 : fg_b1;
    float h0 = b1[u], h1 = b1[u + 64];
    #pragma unroll 8
    for (int c = 0; c < 64; c++) {
        float xc = sx[g][c];
        h0 += xc*__ldg(w1 + c*128 + u);
        h1 += xc*__ldg(w1 + c*128 + u + 64);
    }
    hb[g][u]      = fmaxf(h0, 0.f);
    hb[g][u + 64] = fmaxf(h1, 0.f);
    __syncthreads();

    const float* w2 = bg ? bg_w2 : fg_w2;
    const float* b2 = bg ? bg_b2 : fg_b2;
    float o = s + b2[u];
    #pragma unroll 8
    for (int hh = 0; hh < 128; hh++) o += hb[g][hh]*__ldg(w2 + hh*64 + u);

    g_slot[r*64 + u] = o;
    if (out_slots) out_slots[r*64 + u] = o;
}

// ---------------------------------------------------------------------------
extern "C" void kernel_launch(void* const* d_in, const int* in_sizes, int n_in,
                              void* d_out, int out_size) {
    const float* feat   = (const float*)d_in[0];
    const float* slot   = (const float*)d_in[1];
    const float* nfg    = (const float*)d_in[2];
    const float* nfb    = (const float*)d_in[3];
    const float* Wk     = (const float*)d_in[4];
    const float* Wv     = (const float*)d_in[5];
    const float* qg     = (const float*)d_in[6];
    const float* qb     = (const float*)d_in[7];
    const float* Wq     = (const float*)d_in[8];
    const float* qbgg   = (const float*)d_in[9];
    const float* qbgb   = (const float*)d_in[10];
    const float* Wqbg   = (const float*)d_in[11];
    const float* gwih   = (const float*)d_in[12];
    const float* gwhh   = (const float*)d_in[13];
    const float* gbih   = (const float*)d_in[14];
    const float* gbhh   = (const float*)d_in[15];
    const float* bgwih  = (const float*)d_in[16];
    const float* bgwhh  = (const float*)d_in[17];
    const float* bgbih  = (const float*)d_in[18];
    const float* bgbhh  = (const float*)d_in[19];
    const float* rlng   = (const float*)d_in[20];
    const float* rlnb   = (const float*)d_in[21];
    const float* rw1    = (const float*)d_in[22];
    const float* rb1    = (const float*)d_in[23];
    const float* rw2    = (const float*)d_in[24];
    const float* rb2    = (const float*)d_in[25];
    const float* bglng  = (const float*)d_in[26];
    const float* bglnb  = (const float*)d_in[27];
    const float* bgw1   = (const float*)d_in[28];
    const float* bgb1   = (const float*)d_in[29];
    const float* bgw2   = (const float*)d_in[30];
    const float* bgb2   = (const float*)d_in[31];

    float* out       = (float*)d_out;
    float* out_attn  = out + SLOTS_*D_;   // slots first, then attn

    const int smem_lnkv = (128*128 + 64*128) * (int)sizeof(float);  // 98304 B
    cudaFuncSetAttribute(ln_kv_kernel,
                         cudaFuncAttributeMaxDynamicSharedMemorySize, smem_lnkv);
    const int smem_upd = 4*64*TP_*(int)sizeof(float);  // 66560 B
    cudaFuncSetAttribute(update_kernel,
                         cudaFuncAttributeMaxDynamicSharedMemorySize, smem_upd);

    ln_kv_kernel<<<296, 256, smem_lnkv>>>(feat, nfg, nfb, Wk, Wv);

    for (int it = 0; it < 3; it++) {
        const float* ssrc = (it == 0) ? slot : nullptr;  // null -> g_slot
        q_kernel<<<SLOTS_, 64>>>(ssrc, qg, qb, Wq, qbgg, qbgb, Wqbg);
        attn_kernel<<<dim3(16, B_), 256>>>((it == 2) ? out_attn : nullptr);
        update_kernel<<<B_, 512, smem_upd>>>(ssrc,
            gwih, gwhh, gbih, gbhh,
            bgwih, bgwhh, bgbih, bgbhh,
            rlng, rlnb, rw1, rb1, rw2, rb2,
            bglng, bglnb, bgw1, bgb1, bgw2, bgb2,
            (it == 2) ? out : nullptr);
    }
}